// round 4
// baseline (speedup 1.0000x reference)
#include <cuda_runtime.h>

// self_attention_76416058130984 — GB300 sm_103a
// frames: [4, B=8, C=64, H=160, W=160] fp32 -> out: [8, 256, 160, 160] fp32
//
// Per pixel: E_ij(c) = exp(x_i[c]*x_j[c]) (symmetric, 10 unique per channel),
// denom_i = sum_{j,c} E_ij(c),  out_i[c] = (sum_j E_ij(c)*x_j[c]) / denom_i.
// No max-subtraction needed (logits bounded ~40, fp32 safe; softmax shift-invariant).

#define B_   8
#define C_   64
#define H_   160
#define W_   160
#define HW_  (H_*W_)      // 25600
#define WTILE 32
#define NTHREADS 256
#define SPAD 33           // padded w-stride for conflict-free transposed access

__device__ __forceinline__ float ex2a(float x) {
    float y; asm("ex2.approx.f32 %0, %1;" : "=f"(y) : "f"(x)); return y;
}
__device__ __forceinline__ float rcpa(float x) {
    float y; asm("rcp.approx.f32 %0, %1;" : "=f"(y) : "f"(x)); return y;
}

// 10 unique exps -> row sums r[i] and gated sums y[i]
__device__ __forceinline__ void attn4(const float a[4], float y[4], float r[4]) {
    const float L2E = 1.44269504f;   // log2(e)
    float b0 = a[0]*L2E, b1 = a[1]*L2E, b2 = a[2]*L2E, b3 = a[3]*L2E;
    float e00 = ex2a(a[0]*b0), e01 = ex2a(a[0]*b1), e02 = ex2a(a[0]*b2), e03 = ex2a(a[0]*b3);
    float e11 = ex2a(a[1]*b1), e12 = ex2a(a[1]*b2), e13 = ex2a(a[1]*b3);
    float e22 = ex2a(a[2]*b2), e23 = ex2a(a[2]*b3);
    float e33 = ex2a(a[3]*b3);
    r[0] = (e00+e01)+(e02+e03);
    r[1] = (e01+e11)+(e12+e13);
    r[2] = (e02+e12)+(e22+e23);
    r[3] = (e03+e13)+(e23+e33);
    y[0] = fmaf(e00,a[0], fmaf(e01,a[1], fmaf(e02,a[2], e03*a[3])));
    y[1] = fmaf(e01,a[0], fmaf(e11,a[1], fmaf(e12,a[2], e13*a[3])));
    y[2] = fmaf(e02,a[0], fmaf(e12,a[1], fmaf(e22,a[2], e23*a[3])));
    y[3] = fmaf(e03,a[0], fmaf(e13,a[1], fmaf(e23,a[2], e33*a[3])));
}

__global__ void __launch_bounds__(NTHREADS)
self_attn_fused_kernel(const float* __restrict__ frames, float* __restrict__ out)
{
    // one buffer, reused in place for outputs: [4*64 rows][33]
    __shared__ float s[4*C_*SPAD];

    const int t    = threadIdx.x;
    const int bidx = blockIdx.x;          // B_*H_*(W_/WTILE) = 6400 blocks
    const int tile = bidx % (W_/WTILE);
    const int h    = (bidx / (W_/WTILE)) % H_;
    const int b    = bidx / ((W_/WTILE)*H_);
    const int w0   = tile * WTILE;
    const int sp_in = h*W_ + w0;

    // ---- Phase 1: coalesced load, 4*64 rows of 32 floats (8 x float4 per row)
    #pragma unroll
    for (int it = 0; it < 8; ++it) {
        int f   = t + it*NTHREADS;        // 0..2047
        int row = f >> 3;                 // j*64 + c
        int q   = f & 7;
        int j   = row >> 6;
        int c   = row & 63;
        const float4 v = *reinterpret_cast<const float4*>(
            frames + ((j*B_ + b)*C_ + c)*HW_ + sp_in + q*4);
        float* sp = s + row*SPAD + q*4;
        sp[0] = v.x; sp[1] = v.y; sp[2] = v.z; sp[3] = v.w;
    }
    __syncthreads();

    // ---- Phase 2: each warp owns 4 pixels; lanes = channels (2 per lane)
    const int warp = t >> 5, lane = t & 31;
    #pragma unroll
    for (int pi = 0; pi < 4; ++pi) {
        const int p = warp*4 + pi;
        float a0[4], a1[4];
        #pragma unroll
        for (int j = 0; j < 4; ++j) {
            a0[j] = s[(j*C_ + lane     )*SPAD + p];
            a1[j] = s[(j*C_ + lane + 32)*SPAD + p];
        }
        float y0[4], y1[4], r0[4], r1[4];
        attn4(a0, y0, r0);
        attn4(a1, y1, r1);
        float d[4];
        #pragma unroll
        for (int i = 0; i < 4; ++i) d[i] = r0[i] + r1[i];
        #pragma unroll
        for (int m = 16; m >= 1; m >>= 1) {
            #pragma unroll
            for (int i = 0; i < 4; ++i)
                d[i] += __shfl_xor_sync(0xffffffffu, d[i], m);
        }
        // shfl_xor_sync above also guarantees all lanes finished reading
        // this pixel's column before we overwrite it in place.
        #pragma unroll
        for (int i = 0; i < 4; ++i) {
            const float inv = rcpa(d[i]);
            s[(i*C_ + lane     )*SPAD + p] = y0[i] * inv;
            s[(i*C_ + lane + 32)*SPAD + p] = y1[i] * inv;
        }
    }
    __syncthreads();

    // ---- Phase 3: coalesced store, out[b][row][h][w0..w0+31], row = i*64+c
    const int out_base = (b*4*C_)*HW_ + sp_in;
    #pragma unroll
    for (int it = 0; it < 8; ++it) {
        int f   = t + it*NTHREADS;
        int row = f >> 3;
        int q   = f & 7;
        const float* sp = s + row*SPAD + q*4;
        float4 v = make_float4(sp[0], sp[1], sp[2], sp[3]);
        *reinterpret_cast<float4*>(out + out_base + row*HW_ + q*4) = v;
    }
}

extern "C" void kernel_launch(void* const* d_in, const int* in_sizes, int n_in,
                              void* d_out, int out_size)
{
    const float* frames = (const float*)d_in[0];
    float* out = (float*)d_out;
    const int nblocks = B_ * H_ * (W_/WTILE);   // 6400
    self_attn_fused_kernel<<<nblocks, NTHREADS>>>(frames, out);
}